// round 3
// baseline (speedup 1.0000x reference)
#include <cuda_runtime.h>
#include <cuda_bf16.h>

// Problem constants: shape (2,3,512,512) fp32, KS=5, PAD=2, ALPHA1=0.1, ALPHA2=1.5, EPS=1e-8
#define HH 512
#define WW 512
#define NPLANE 6
#define NPIX (HH * WW)
#define NTOT (NPLANE * NPIX)           // 1,572,864 per tensor

#define GX 16                           // 512/32
#define GY 64                           // 512/8
#define NBLOCKS (GX * GY * NPLANE)      // 6144

__device__ int          g_negflag[2];
__device__ unsigned int g_count;
__device__ float        g_partials[NBLOCKS];

typedef unsigned long long u64;

// ---------------------------------------------------------------------------
// packed f32x2 helpers (sm_100a native; doubles FMA-pipe throughput)
__device__ __forceinline__ u64 pk2(float lo, float hi) {
    u64 r; asm("mov.b64 %0, {%1, %2};" : "=l"(r) : "f"(lo), "f"(hi)); return r;
}
__device__ __forceinline__ void upk2(u64 v, float& lo, float& hi) {
    asm("mov.b64 {%0, %1}, %2;" : "=f"(lo), "=f"(hi) : "l"(v));
}
__device__ __forceinline__ u64 add2(u64 a, u64 b) {
    u64 r; asm("add.rn.f32x2 %0, %1, %2;" : "=l"(r) : "l"(a), "l"(b)); return r;
}
__device__ __forceinline__ u64 mul2(u64 a, u64 b) {
    u64 r; asm("mul.rn.f32x2 %0, %1, %2;" : "=l"(r) : "l"(a), "l"(b)); return r;
}
__device__ __forceinline__ u64 fma2(u64 a, u64 b, u64 c) {
    u64 r; asm("fma.rn.f32x2 %0, %1, %2, %3;" : "=l"(r) : "l"(a), "l"(b), "l"(c)); return r;
}
__device__ __forceinline__ float ex2f(float x) {
    float y; asm("ex2.approx.ftz.f32 %0, %1;" : "=f"(y) : "f"(x)); return y;
}

__device__ __forceinline__ int reflect(int i) {
    // jnp.pad mode='reflect', pad=2, dim=512:  -1->1, -2->2, 512->510, 513->509
    return (i < 0) ? -i : ((i >= HH) ? (2 * HH - 2 - i) : i);
}

// ---------------------------------------------------------------------------
__global__ void init_kernel() {
    g_negflag[0] = 0;
    g_negflag[1] = 0;
    g_count      = 0;
}

// "img.min() < 0" <=> any element < 0. Early-exit once both flags are set.
__global__ __launch_bounds__(256) void flag_kernel(const float4* __restrict__ a,
                                                   const float4* __restrict__ b,
                                                   int n4) {
    const int stride = gridDim.x * blockDim.x;
    volatile int* vf = g_negflag;
    for (int i = blockIdx.x * blockDim.x + threadIdx.x; i < n4; i += stride) {
        if (vf[0] && vf[1]) return;   // both established -> nothing left to learn
        float4 va = a[i];
        float4 vb = b[i];
        int fa = (va.x < 0.f) | (va.y < 0.f) | (va.z < 0.f) | (va.w < 0.f);
        int fb = (vb.x < 0.f) | (vb.y < 0.f) | (vb.z < 0.f) | (vb.w < 0.f);
        if (__any_sync(0xffffffffu, fa) && ((threadIdx.x & 31) == 0)) g_negflag[0] = 1;
        if (__any_sync(0xffffffffu, fb) && ((threadIdx.x & 31) == 0)) g_negflag[1] = 1;
    }
}

// ---------------------------------------------------------------------------
// Fused: bilateral(A), bilateral(B) via packed f32x2, |diff|, block partial sum,
// and (in the last block to finish) the deterministic final reduction.
__global__ __launch_bounds__(256) void bilat_kernel(const float* __restrict__ A,
                                                    const float* __restrict__ B,
                                                    float* __restrict__ out) {
    __shared__ float2 sT[12][36];       // .x = A-plane value, .y = B-plane value
    __shared__ float  swarp[8];
    __shared__ int    s_islast;

    const int tx  = threadIdx.x;        // 0..31
    const int ty  = threadIdx.y;        // 0..7
    const int tid = ty * 32 + tx;
    const int x0  = blockIdx.x * 32;
    const int y0  = blockIdx.y * 8;
    const int plane = blockIdx.z;

    const float sclA = g_negflag[0] ? 0.5f : 1.0f;
    const float bseA = g_negflag[0] ? 0.5f : 0.0f;
    const float sclB = g_negflag[1] ? 0.5f : 1.0f;
    const float bseB = g_negflag[1] ? 0.5f : 0.0f;

    const float* __restrict__ Ap = A + plane * NPIX;
    const float* __restrict__ Bp = B + plane * NPIX;

    // cooperative halo load (reflect at borders), normalized at load time
#pragma unroll
    for (int idx = tid; idx < 12 * 36; idx += 256) {
        int r  = idx / 36;
        int c  = idx - r * 36;
        int gy = reflect(y0 - 2 + r);
        int gx = reflect(x0 - 2 + c);
        int g  = gy * WW + gx;
        sT[r][c] = make_float2(fmaf(__ldg(Ap + g), sclA, bseA),
                               fmaf(__ldg(Bp + g), sclB, bseB));
    }
    __syncthreads();

    const u64* __restrict__ sTu = reinterpret_cast<const u64*>(&sT[0][0]);

    const float L2E  = 1.4426950408889634f;
    const float NEGK = -5.0f * L2E;            // -(1/(2*alpha1)) * log2(e)
    const u64 NEGK2  = pk2(NEGK, NEGK);

    // 6 distinct spatial offsets: (dy-2)^2+(dx-2)^2 in {0,1,2,4,5,8}
    u64 OFFN[6];
    {
        const float sv[6] = {0.f, 1.f, 2.f, 4.f, 5.f, 8.f};
#pragma unroll
        for (int i = 0; i < 6; i++) {
            float o = -sv[i] * (L2E / 3.0f);   // -(s)/(2*alpha2) * log2e
            OFFN[i] = pk2(o, o);
        }
    }

    float2 ctr = sT[ty + 2][tx + 2];
    const u64 nc = pk2(-ctr.x, -ctr.y);        // negated packed center

    u64 ws = pk2(0.f, 0.f);
    u64 ac = ws;

    const int base = ty * 36 + tx;
#pragma unroll
    for (int dy = 0; dy < 5; dy++) {
#pragma unroll
        for (int dx = 0; dx < 5; dx++) {
            const int s = (dy - 2) * (dy - 2) + (dx - 2) * (dx - 2);
            const int oi = (s == 0) ? 0 : (s == 1) ? 1 : (s == 2) ? 2
                         : (s == 4) ? 3 : (s == 5) ? 4 : 5;
            u64 p = sTu[base + dy * 36 + dx];          // LDS.64 (pa, pb)
            u64 d = add2(p, nc);                       // p - c
            u64 t = mul2(d, d);                        // d^2
            u64 g = fma2(t, NEGK2, OFFN[oi]);          // log2-domain exponent
            float ga, gb;
            upk2(g, ga, gb);
            u64 w = pk2(ex2f(ga), ex2f(gb));
            ws = add2(ws, w);
            ac = fma2(w, p, ac);
        }
    }

    float wsa, wsb, aca, acb;
    upk2(ws, wsa, wsb);
    upk2(ac, aca, acb);
    float fa = __fdividef(aca, wsa + 1e-8f);
    float fb = __fdividef(acb, wsb + 1e-8f);
    float v  = fabsf(fa - fb);

    // deterministic block reduction
#pragma unroll
    for (int o = 16; o > 0; o >>= 1) v += __shfl_down_sync(0xffffffffu, v, o);
    if ((tid & 31) == 0) swarp[tid >> 5] = v;
    __syncthreads();
    if (tid < 8) {
        float t = swarp[tid];
#pragma unroll
        for (int o = 4; o > 0; o >>= 1) t += __shfl_down_sync(0x000000ffu, t, o);
        if (tid == 0) {
            int bidx = (blockIdx.z * gridDim.y + blockIdx.y) * gridDim.x + blockIdx.x;
            g_partials[bidx] = t;
            __threadfence();
            unsigned int done = atomicAdd(&g_count, 1u);
            s_islast = (done == (unsigned int)(NBLOCKS - 1));
        }
    }
    __syncthreads();

    // last block: deterministic final reduction over L2-hot partials
    if (s_islast) {
        const float4* p4 = reinterpret_cast<const float4*>(g_partials);
        float s = 0.f;
#pragma unroll
        for (int i = 0; i < NBLOCKS / 4 / 256; i++) {      // 6 float4 per thread
            float4 x = p4[tid + i * 256];
            s += (x.x + x.y) + (x.z + x.w);
        }
#pragma unroll
        for (int o = 16; o > 0; o >>= 1) s += __shfl_down_sync(0xffffffffu, s, o);
        if ((tid & 31) == 0) swarp[tid >> 5] = s;
        __syncthreads();
        if (tid < 8) {
            float t = swarp[tid];
#pragma unroll
            for (int o = 4; o > 0; o >>= 1) t += __shfl_down_sync(0x000000ffu, t, o);
            if (tid == 0) out[0] = t * (1.0f / (float)NTOT);
        }
    }
}

// ---------------------------------------------------------------------------
extern "C" void kernel_launch(void* const* d_in, const int* in_sizes, int n_in,
                              void* d_out, int out_size) {
    const float* A = (const float*)d_in[0];   // output
    const float* B = (const float*)d_in[1];   // target
    float* out = (float*)d_out;

    init_kernel<<<1, 1>>>();
    flag_kernel<<<148, 256>>>((const float4*)A, (const float4*)B, NTOT / 4);

    dim3 grid(GX, GY, NPLANE);
    dim3 block(32, 8);
    bilat_kernel<<<grid, block>>>(A, B, out);
}

// round 4
// speedup vs baseline: 2.8275x; 2.8275x over previous
#include <cuda_runtime.h>
#include <cuda_bf16.h>

// Problem constants: shape (2,3,512,512) fp32, KS=5, PAD=2, ALPHA1=0.1, ALPHA2=1.5, EPS=1e-8
#define HH 512
#define WW 512
#define NPLANE 6
#define NPIX (HH * WW)
#define NTOT (NPLANE * NPIX)           // 1,572,864 per tensor

#define GX 16                           // 512/32
#define GY 64                           // 512/8
#define NBLOCKS (GX * GY * NPLANE)      // 6144

// __device__ globals are zero-initialized at module load; bilat's last block
// resets them after use, so every graph replay starts clean with NO init kernel.
__device__ int          g_negflag[2];
__device__ unsigned int g_count;
__device__ float        g_partials[NBLOCKS];

// ---------------------------------------------------------------------------
__device__ __forceinline__ float ex2f(float x) {
    float y; asm("ex2.approx.ftz.f32 %0, %1;" : "=f"(y) : "f"(x)); return y;
}

__device__ __forceinline__ int reflect(int i) {
    // jnp.pad mode='reflect', pad=2, dim=512:  -1->1, -2->2, 512->510, 513->509
    return (i < 0) ? -i : ((i >= HH) ? (2 * HH - 2 - i) : i);
}

// ---------------------------------------------------------------------------
// "img.min() < 0" <=> any element < 0.  Plain full scan, NO same-address
// polling (Round-3's volatile early-exit serialized on one L2 slice).
__global__ __launch_bounds__(256) void flag_kernel(const float4* __restrict__ a,
                                                   const float4* __restrict__ b,
                                                   int n4) {
    int fa = 0, fb = 0;
    const int stride = gridDim.x * blockDim.x;
    for (int i = blockIdx.x * blockDim.x + threadIdx.x; i < n4; i += stride) {
        float4 va = a[i];
        float4 vb = b[i];
        fa |= (va.x < 0.f) | (va.y < 0.f) | (va.z < 0.f) | (va.w < 0.f);
        fb |= (vb.x < 0.f) | (vb.y < 0.f) | (vb.z < 0.f) | (vb.w < 0.f);
    }
    // one store per warp that saw a negative (benign: only 0->1 transitions)
    if (__any_sync(0xffffffffu, fa) && ((threadIdx.x & 31) == 0)) g_negflag[0] = 1;
    if (__any_sync(0xffffffffu, fb) && ((threadIdx.x & 31) == 0)) g_negflag[1] = 1;
}

// ---------------------------------------------------------------------------
// Fused bilateral(A), bilateral(B), |diff| partial sum, and (in the last block
// to finish) the deterministic final reduction + state reset for next replay.
__global__ __launch_bounds__(256) void bilat_kernel(const float* __restrict__ A,
                                                    const float* __restrict__ B,
                                                    float* __restrict__ out) {
    __shared__ float sA[12][36];
    __shared__ float sB[12][36];
    __shared__ float swarp[8];
    __shared__ int   s_islast;

    const int tx  = threadIdx.x;        // 0..31
    const int ty  = threadIdx.y;        // 0..7
    const int tid = ty * 32 + tx;
    const int x0  = blockIdx.x * 32;
    const int y0  = blockIdx.y * 8;
    const int plane = blockIdx.z;

    const float sclA = g_negflag[0] ? 0.5f : 1.0f;
    const float bseA = g_negflag[0] ? 0.5f : 0.0f;
    const float sclB = g_negflag[1] ? 0.5f : 1.0f;
    const float bseB = g_negflag[1] ? 0.5f : 0.0f;

    const float* __restrict__ Ap = A + plane * NPIX;
    const float* __restrict__ Bp = B + plane * NPIX;

    // cooperative halo load (reflect at borders), normalized at load time
#pragma unroll
    for (int idx = tid; idx < 12 * 36; idx += 256) {
        int r  = idx / 36;
        int c  = idx - r * 36;
        int gy = reflect(y0 - 2 + r);
        int gx = reflect(x0 - 2 + c);
        int g  = gy * WW + gx;
        sA[r][c] = fmaf(__ldg(Ap + g), sclA, bseA);
        sB[r][c] = fmaf(__ldg(Bp + g), sclB, bseB);
    }
    __syncthreads();

    const float ca = sA[ty + 2][tx + 2];
    const float cb = sB[ty + 2][tx + 2];

    float wsA = 0.f, acA = 0.f, wsB = 0.f, acB = 0.f;

    const float L2E  = 1.4426950408889634f;
    const float NEGK = -5.0f * L2E;            // -(1/(2*alpha1)) * log2(e)

#pragma unroll
    for (int dy = 0; dy < 5; dy++) {
#pragma unroll
        for (int dx = 0; dx < 5; dx++) {
            // spatial term folded into exponent (log2 domain), compile-time const
            const float off = (float)((dy - 2) * (dy - 2) + (dx - 2) * (dx - 2))
                              * (L2E / 3.0f);   // (gx^2+gy^2)/(2*alpha2) * log2e

            float pa = sA[ty + dy][tx + dx];
            float da = pa - ca;
            float wa = ex2f(fmaf(da * da, NEGK, -off));
            wsA += wa;
            acA  = fmaf(wa, pa, acA);

            float pb = sB[ty + dy][tx + dx];
            float db = pb - cb;
            float wb = ex2f(fmaf(db * db, NEGK, -off));
            wsB += wb;
            acB  = fmaf(wb, pb, acB);
        }
    }

    float fa = __fdividef(acA, wsA + 1e-8f);
    float fb = __fdividef(acB, wsB + 1e-8f);
    float v  = fabsf(fa - fb);

    // deterministic block reduction
#pragma unroll
    for (int o = 16; o > 0; o >>= 1) v += __shfl_down_sync(0xffffffffu, v, o);
    if ((tid & 31) == 0) swarp[tid >> 5] = v;
    __syncthreads();
    if (tid == 0) {
        float t = 0.f;
#pragma unroll
        for (int w = 0; w < 8; w++) t += swarp[w];
        int bidx = (blockIdx.z * gridDim.y + blockIdx.y) * gridDim.x + blockIdx.x;
        g_partials[bidx] = t;
        __threadfence();
        unsigned int done = atomicAdd(&g_count, 1u);
        s_islast = (done == (unsigned int)(NBLOCKS - 1));
    }
    __syncthreads();

    // last block: deterministic final reduction over L2-hot partials, then
    // reset device state so the next graph replay starts clean.
    if (s_islast) {
        const float4* p4 = reinterpret_cast<const float4*>(g_partials);
        float s = 0.f;
#pragma unroll
        for (int i = 0; i < NBLOCKS / 4 / 256; i++) {      // 6 float4 per thread
            float4 x = p4[tid + i * 256];
            s += (x.x + x.y) + (x.z + x.w);
        }
#pragma unroll
        for (int o = 16; o > 0; o >>= 1) s += __shfl_down_sync(0xffffffffu, s, o);
        if ((tid & 31) == 0) swarp[tid >> 5] = s;
        __syncthreads();
        if (tid == 0) {
            float t = 0.f;
#pragma unroll
            for (int w = 0; w < 8; w++) t += swarp[w];
            out[0] = t * (1.0f / (float)NTOT);
            g_negflag[0] = 0;              // self-clean for next replay
            g_negflag[1] = 0;
            g_count      = 0;
        }
    }
}

// ---------------------------------------------------------------------------
extern "C" void kernel_launch(void* const* d_in, const int* in_sizes, int n_in,
                              void* d_out, int out_size) {
    const float* A = (const float*)d_in[0];   // output
    const float* B = (const float*)d_in[1];   // target
    float* out = (float*)d_out;

    flag_kernel<<<256, 256>>>((const float4*)A, (const float4*)B, NTOT / 4);

    dim3 grid(GX, GY, NPLANE);
    dim3 block(32, 8);
    bilat_kernel<<<grid, block>>>(A, B, out);
}

// round 6
// speedup vs baseline: 2.9838x; 1.0553x over previous
#include <cuda_runtime.h>
#include <cuda_bf16.h>

// Problem constants: shape (2,3,512,512) fp32, KS=5, PAD=2, ALPHA1=0.1, ALPHA2=1.5, EPS=1e-8
#define HH 512
#define WW 512
#define NPLANE 6
#define NPIX (HH * WW)
#define NTOT (NPLANE * NPIX)           // 1,572,864 per tensor

// bilat block: 32x8 threads, each thread computes 4 pixels in y -> 32x32 tile
#define GXB 16                          // 512/32
#define GYB 16                          // 512/32
#define NBLOCKS (GXB * GYB * NPLANE)    // 1536

// __device__ globals are zero-initialized at module load; bilat's last block
// resets them after use, so every graph replay starts clean with NO init kernel.
__device__ int          g_negflag[2];
__device__ unsigned int g_count;
__device__ float        g_partials[NBLOCKS];

// ---------------------------------------------------------------------------
__device__ __forceinline__ float ex2f(float x) {
    float y; asm("ex2.approx.ftz.f32 %0, %1;" : "=f"(y) : "f"(x)); return y;
}

__device__ __forceinline__ int reflect(int i) {
    // jnp.pad mode='reflect', pad=2, dim=512:  -1->1, -2->2, 512->510, 513->509
    return (i < 0) ? -i : ((i >= HH) ? (2 * HH - 2 - i) : i);
}

// ---------------------------------------------------------------------------
// "img.min() < 0" <=> any element < 0.  Plain full scan (no same-address polling).
__global__ __launch_bounds__(256) void flag_kernel(const float4* __restrict__ a,
                                                   const float4* __restrict__ b,
                                                   int n4) {
    int fa = 0, fb = 0;
    const int stride = gridDim.x * blockDim.x;
    for (int i = blockIdx.x * blockDim.x + threadIdx.x; i < n4; i += stride) {
        float4 va = a[i];
        float4 vb = b[i];
        fa |= (va.x < 0.f) | (va.y < 0.f) | (va.z < 0.f) | (va.w < 0.f);
        fb |= (vb.x < 0.f) | (vb.y < 0.f) | (vb.z < 0.f) | (vb.w < 0.f);
    }
    if (__any_sync(0xffffffffu, fa) && ((threadIdx.x & 31) == 0)) g_negflag[0] = 1;
    if (__any_sync(0xffffffffu, fb) && ((threadIdx.x & 31) == 0)) g_negflag[1] = 1;
}

// ---------------------------------------------------------------------------
// Fused bilateral(A), bilateral(B), |diff| partial sum, last-block final
// reduction + state reset.  float2-packed smem (one LDS.64 feeds both
// tensors); 4-way y-coarsening (each loaded value feeds up to 4 windows).
__global__ __launch_bounds__(256) void bilat_kernel(const float* __restrict__ A,
                                                    const float* __restrict__ B,
                                                    float* __restrict__ out) {
    __shared__ float2 sT[36][36];       // .x = A value, .y = B value (10.1 KB)
    __shared__ float  swarp[8];
    __shared__ int    s_islast;

    const int tx  = threadIdx.x;        // 0..31
    const int ty  = threadIdx.y;        // 0..7
    const int tid = ty * 32 + tx;
    const int x0  = blockIdx.x * 32;
    const int y0  = blockIdx.y * 32;
    const int plane = blockIdx.z;

    const float sclA = g_negflag[0] ? 0.5f : 1.0f;
    const float bseA = g_negflag[0] ? 0.5f : 0.0f;
    const float sclB = g_negflag[1] ? 0.5f : 1.0f;
    const float bseB = g_negflag[1] ? 0.5f : 0.0f;

    const float* __restrict__ Ap = A + plane * NPIX;
    const float* __restrict__ Bp = B + plane * NPIX;

    // cooperative halo load: 36x36 tile (reflect at borders), normalized at load
    for (int idx = tid; idx < 36 * 36; idx += 256) {
        int r  = idx / 36;
        int c  = idx - r * 36;
        int gy = reflect(y0 - 2 + r);
        int gx = reflect(x0 - 2 + c);
        int g  = gy * WW + gx;
        sT[r][c] = make_float2(fmaf(__ldg(Ap + g), sclA, bseA),
                               fmaf(__ldg(Bp + g), sclB, bseB));
    }
    __syncthreads();

    const float L2E  = 1.4426950408889634f;
    const float NEGK = -5.0f * L2E;            // -(1/(2*alpha1)) * log2(e)

    // 4 output pixels per thread: tile rows 4ty .. 4ty+3 (smem center rows +2)
    float2 ctr[4];
#pragma unroll
    for (int o = 0; o < 4; o++) ctr[o] = sT[4 * ty + o + 2][tx + 2];

    float wsA[4], acA[4], wsB[4], acB[4];
#pragma unroll
    for (int o = 0; o < 4; o++) { wsA[o] = acA[o] = wsB[o] = acB[o] = 0.f; }

#pragma unroll
    for (int dy = 0; dy < 8; dy++) {           // smem rows 4ty+dy
#pragma unroll
        for (int dx = 0; dx < 5; dx++) {
            float2 p = sT[4 * ty + dy][tx + dx];   // one LDS.64, both tensors
#pragma unroll
            for (int o = 0; o < 4; o++) {
                const int rel = dy - o;            // row offset within o's window
                if (rel < 0 || rel > 4) continue;
                // spatial term folded into exponent (log2 domain), comptime const
                const float off = (float)((rel - 2) * (rel - 2) +
                                          (dx - 2) * (dx - 2)) * (L2E / 3.0f);

                float da = p.x - ctr[o].x;
                float wa = ex2f(fmaf(da * da, NEGK, -off));
                wsA[o] += wa;
                acA[o]  = fmaf(wa, p.x, acA[o]);

                float db = p.y - ctr[o].y;
                float wb = ex2f(fmaf(db * db, NEGK, -off));
                wsB[o] += wb;
                acB[o]  = fmaf(wb, p.y, acB[o]);
            }
        }
    }

    float v = 0.f;
#pragma unroll
    for (int o = 0; o < 4; o++) {
        float fa = __fdividef(acA[o], wsA[o] + 1e-8f);
        float fb = __fdividef(acB[o], wsB[o] + 1e-8f);
        v += fabsf(fa - fb);
    }

    // deterministic block reduction
#pragma unroll
    for (int o = 16; o > 0; o >>= 1) v += __shfl_down_sync(0xffffffffu, v, o);
    if ((tid & 31) == 0) swarp[tid >> 5] = v;
    __syncthreads();
    if (tid == 0) {
        float t = 0.f;
#pragma unroll
        for (int w = 0; w < 8; w++) t += swarp[w];
        int bidx = (blockIdx.z * gridDim.y + blockIdx.y) * gridDim.x + blockIdx.x;
        g_partials[bidx] = t;
        __threadfence();
        unsigned int done = atomicAdd(&g_count, 1u);
        s_islast = (done == (unsigned int)(NBLOCKS - 1));
    }
    __syncthreads();

    // last block: deterministic final reduction over L2-hot partials, then
    // reset device state so the next graph replay starts clean.
    if (s_islast) {
        float s = 0.f;
#pragma unroll
        for (int i = 0; i < NBLOCKS / 256; i++)     // 6 scalars per thread
            s += g_partials[tid + i * 256];
#pragma unroll
        for (int o = 16; o > 0; o >>= 1) s += __shfl_down_sync(0xffffffffu, s, o);
        if ((tid & 31) == 0) swarp[tid >> 5] = s;
        __syncthreads();
        if (tid == 0) {
            float t = 0.f;
#pragma unroll
            for (int w = 0; w < 8; w++) t += swarp[w];
            out[0] = t * (1.0f / (float)NTOT);
            g_negflag[0] = 0;              // self-clean for next replay
            g_negflag[1] = 0;
            g_count      = 0;
        }
    }
}

// ---------------------------------------------------------------------------
extern "C" void kernel_launch(void* const* d_in, const int* in_sizes, int n_in,
                              void* d_out, int out_size) {
    const float* A = (const float*)d_in[0];   // output
    const float* B = (const float*)d_in[1];   // target
    float* out = (float*)d_out;

    flag_kernel<<<256, 256>>>((const float4*)A, (const float4*)B, NTOT / 4);

    dim3 grid(GXB, GYB, NPLANE);
    dim3 block(32, 8);
    bilat_kernel<<<grid, block>>>(A, B, out);
}

// round 7
// speedup vs baseline: 3.0447x; 1.0204x over previous
#include <cuda_runtime.h>
#include <cuda_bf16.h>

// Problem constants: shape (2,3,512,512) fp32, KS=5, PAD=2, ALPHA1=0.1, ALPHA2=1.5, EPS=1e-8
#define HH 512
#define WW 512
#define NPLANE 6
#define NPIX (HH * WW)
#define NTOT (NPLANE * NPIX)           // 1,572,864 per tensor

// bilat block: 32x8 threads, each thread computes 4 pixels in y -> 32x32 tile
#define GXB 16                          // 512/32
#define GYB 16                          // 512/32
#define NBLOCKS (GXB * GYB * NPLANE)    // 1536

// __device__ globals are zero-initialized at module load; bilat's last block
// resets them after use, so every graph replay starts clean with NO init kernel.
__device__ int          g_negflag[2];
__device__ unsigned int g_count;
__device__ float        g_partials[NBLOCKS];

#define L2E  1.4426950408889634f
#define NEGK (-5.0f * L2E)             // -(1/(2*alpha1)) * log2(e)

// ---------------------------------------------------------------------------
__device__ __forceinline__ float ex2f(float x) {
    float y; asm("ex2.approx.ftz.f32 %0, %1;" : "=f"(y) : "f"(x)); return y;
}

__device__ __forceinline__ int reflect(int i) {
    // jnp.pad mode='reflect', pad=2, dim=512:  -1->1, -2->2, 512->510, 513->509
    return (i < 0) ? -i : ((i >= HH) ? (2 * HH - 2 - i) : i);
}

// spatial gaussian exp(-s/3) for s = (rel-2)^2 + (dx-2)^2, as a compile-time
// immediate multiplier (moved out of the exponent; exact same math since the
// per-window constant factor exp2(NEGK*c^2) cancels in the ratio sum(wp)/sum(w))
__device__ __forceinline__ constexpr float spatialS(int s) {
    // e^(-s/3) for s in {0,1,2,4,5,8}
    return (s == 0) ? 1.0f
         : (s == 1) ? 0.71653131f
         : (s == 2) ? 0.51341712f
         : (s == 4) ? 0.26359714f
         : (s == 5) ? 0.18887560f
         :            0.06948345f;
}

// ---------------------------------------------------------------------------
// "img.min() < 0" <=> any element < 0.  Plain full scan (no same-address polling).
__global__ __launch_bounds__(256) void flag_kernel(const float4* __restrict__ a,
                                                   const float4* __restrict__ b,
                                                   int n4) {
    int fa = 0, fb = 0;
    const int stride = gridDim.x * blockDim.x;
    for (int i = blockIdx.x * blockDim.x + threadIdx.x; i < n4; i += stride) {
        float4 va = a[i];
        float4 vb = b[i];
        fa |= (va.x < 0.f) | (va.y < 0.f) | (va.z < 0.f) | (va.w < 0.f);
        fb |= (vb.x < 0.f) | (vb.y < 0.f) | (vb.z < 0.f) | (vb.w < 0.f);
    }
    if (__any_sync(0xffffffffu, fa) && ((threadIdx.x & 31) == 0)) g_negflag[0] = 1;
    if (__any_sync(0xffffffffu, fb) && ((threadIdx.x & 31) == 0)) g_negflag[1] = 1;
}

// ---------------------------------------------------------------------------
// Fused bilateral(A), bilateral(B), |diff| partial sum, last-block final
// reduction + state reset.  smem holds (p, NEGK*p^2) for both tensors so the
// exponent is a single FFMA per tap: arg = q + K1[o]*p,  K1[o] = -2*NEGK*c[o].
__global__ __launch_bounds__(256) void bilat_kernel(const float* __restrict__ A,
                                                    const float* __restrict__ B,
                                                    float* __restrict__ out) {
    __shared__ float4 sT[36][36];       // (pA, NEGK*pA^2, pB, NEGK*pB^2), 20.7KB
    __shared__ float  swarp[8];
    __shared__ int    s_islast;

    const int tx  = threadIdx.x;        // 0..31
    const int ty  = threadIdx.y;        // 0..7
    const int tid = ty * 32 + tx;
    const int x0  = blockIdx.x * 32;
    const int y0  = blockIdx.y * 32;
    const int plane = blockIdx.z;

    const float sclA = g_negflag[0] ? 0.5f : 1.0f;
    const float bseA = g_negflag[0] ? 0.5f : 0.0f;
    const float sclB = g_negflag[1] ? 0.5f : 1.0f;
    const float bseB = g_negflag[1] ? 0.5f : 0.0f;

    const float* __restrict__ Ap = A + plane * NPIX;
    const float* __restrict__ Bp = B + plane * NPIX;

    // cooperative halo load: 36x36 tile (reflect at borders), normalized, with
    // q = NEGK*p^2 precomputed once per loaded pixel
    for (int idx = tid; idx < 36 * 36; idx += 256) {
        int r  = idx / 36;
        int c  = idx - r * 36;
        int gy = reflect(y0 - 2 + r);
        int gx = reflect(x0 - 2 + c);
        int g  = gy * WW + gx;
        float pa = fmaf(__ldg(Ap + g), sclA, bseA);
        float pb = fmaf(__ldg(Bp + g), sclB, bseB);
        sT[r][c] = make_float4(pa, NEGK * pa * pa, pb, NEGK * pb * pb);
    }
    __syncthreads();

    // 4 output pixels per thread: tile rows 4ty .. 4ty+3 (smem center rows +2)
    float K1A[4], K1B[4];
#pragma unroll
    for (int o = 0; o < 4; o++) {
        float4 c = sT[4 * ty + o + 2][tx + 2];
        K1A[o] = -2.0f * NEGK * c.x;    // +10*log2e * cA
        K1B[o] = -2.0f * NEGK * c.z;
    }

    float wsA[4], acA[4], wsB[4], acB[4];
#pragma unroll
    for (int o = 0; o < 4; o++) { wsA[o] = acA[o] = wsB[o] = acB[o] = 0.f; }

#pragma unroll
    for (int dy = 0; dy < 8; dy++) {           // smem rows 4ty+dy
#pragma unroll
        for (int dx = 0; dx < 5; dx++) {
            float4 p = sT[4 * ty + dy][tx + dx];   // one LDS.128, both tensors
#pragma unroll
            for (int o = 0; o < 4; o++) {
                const int rel = dy - o;            // row offset within o's window
                if (rel < 0 || rel > 4) continue;
                const float S = spatialS((rel - 2) * (rel - 2) +
                                         (dx - 2) * (dx - 2));   // imm multiplier

                float ewa = ex2f(fmaf(p.x, K1A[o], p.y));  // range term (scaled)
                wsA[o] = fmaf(ewa, S, wsA[o]);
                acA[o] = fmaf(ewa * p.x, S, acA[o]);

                float ewb = ex2f(fmaf(p.z, K1B[o], p.w));
                wsB[o] = fmaf(ewb, S, wsB[o]);
                acB[o] = fmaf(ewb * p.z, S, acB[o]);
            }
        }
    }

    // per-window constant factor exp2(NEGK*c^2) cancels in the ratio; EPS is a
    // fp32 no-op in the reference (wsum >= 1 there), so plain divide is exact.
    float v = 0.f;
#pragma unroll
    for (int o = 0; o < 4; o++) {
        float fa = __fdividef(acA[o], wsA[o]);
        float fb = __fdividef(acB[o], wsB[o]);
        v += fabsf(fa - fb);
    }

    // deterministic block reduction
#pragma unroll
    for (int o = 16; o > 0; o >>= 1) v += __shfl_down_sync(0xffffffffu, v, o);
    if ((tid & 31) == 0) swarp[tid >> 5] = v;
    __syncthreads();
    if (tid == 0) {
        float t = 0.f;
#pragma unroll
        for (int w = 0; w < 8; w++) t += swarp[w];
        int bidx = (blockIdx.z * gridDim.y + blockIdx.y) * gridDim.x + blockIdx.x;
        g_partials[bidx] = t;
        __threadfence();
        unsigned int done = atomicAdd(&g_count, 1u);
        s_islast = (done == (unsigned int)(NBLOCKS - 1));
    }
    __syncthreads();

    // last block: deterministic final reduction over L2-hot partials, then
    // reset device state so the next graph replay starts clean.
    if (s_islast) {
        float s = 0.f;
#pragma unroll
        for (int i = 0; i < NBLOCKS / 256; i++)     // 6 scalars per thread
            s += g_partials[tid + i * 256];
#pragma unroll
        for (int o = 16; o > 0; o >>= 1) s += __shfl_down_sync(0xffffffffu, s, o);
        if ((tid & 31) == 0) swarp[tid >> 5] = s;
        __syncthreads();
        if (tid == 0) {
            float t = 0.f;
#pragma unroll
            for (int w = 0; w < 8; w++) t += swarp[w];
            out[0] = t * (1.0f / (float)NTOT);
            g_negflag[0] = 0;              // self-clean for next replay
            g_negflag[1] = 0;
            g_count      = 0;
        }
    }
}

// ---------------------------------------------------------------------------
extern "C" void kernel_launch(void* const* d_in, const int* in_sizes, int n_in,
                              void* d_out, int out_size) {
    const float* A = (const float*)d_in[0];   // output
    const float* B = (const float*)d_in[1];   // target
    float* out = (float*)d_out;

    flag_kernel<<<256, 256>>>((const float4*)A, (const float4*)B, NTOT / 4);

    dim3 grid(GXB, GYB, NPLANE);
    dim3 block(32, 8);
    bilat_kernel<<<grid, block>>>(A, B, out);
}